// round 14
// baseline (speedup 1.0000x reference)
#include <cuda_runtime.h>
#include <cuda_bf16.h>
#include <math.h>

// ---------------------------------------------------------------------------
// GNNModel: hyperbolic GNN message passing (c = 1e-6)
//
// Edge path: with c=1e-6 and data scale 0.1, expmap0/mobius/logmap0 are
// identity to O(1e-6) relative (tolerance 1e-3):
//   message = sigmoid(attn) * (hidden[sub] + rela_embed[rel])
// Final per-node transform keeps exact math via split-bf16 tensor-core GEMM.
// Edge indices repacked to 8B/edge (sub|rel<<17, obj|r_idx<<17) in prep's
// latency shadow — cuts the edge kernel's LTS byte floor.
// ---------------------------------------------------------------------------

#define MAX_NODE 100000
#define MAX_VOCAB 512
#define MAX_B 256
#define MAX_EDGE (1 << 20)
#define DD 64

// attention tables in bf16 (only feed sigmoid(relu(.)@Wattn) — error << 1e-3)
__device__ __align__(16) __nv_bfloat16 g_hs_projh [MAX_NODE * DD];
__device__ __align__(16) __nv_bfloat16 g_rel_projh[MAX_VOCAB * DD];
__device__ __align__(16) __nv_bfloat16 g_qr_projh [MAX_B * DD];
__device__ __align__(16) uint2 g_epack[MAX_EDGE];   // packed edge indices

#define SC 1.0e-3f                    // sqrt(c), c = 1e-6
#define CC 1.0e-6f
#define MAXNORM (0.996f / SC)
#define MN2 (MAXNORM * MAXNORM)

// bf16 pair (packed in u32) -> two f32, pure ALU
__device__ __forceinline__ float bflo(unsigned u) { return __uint_as_float(u << 16); }
__device__ __forceinline__ float bfhi(unsigned u) { return __uint_as_float(u & 0xffff0000u); }

// artanh(z)/z as poly in z^2 (valid z^2 < 0.09, guarded fallback above)
__device__ __forceinline__ float artanh_ratio(float z2) {
    float f = fmaf(z2, fmaf(z2, fmaf(z2, fmaf(z2, 1.0f/9.0f, 1.0f/7.0f),
                                     0.2f), 1.0f/3.0f), 1.0f);
    if (z2 > 0.09f) {
        float z = sqrtf(z2);
        float zc = fminf(z, 1.0f - 1e-5f);
        f = 0.5f * (log1pf(zc) - log1pf(-zc)) / z;
    }
    return f;
}
// tanh(z)/z as poly in z^2 (valid z^2 < 0.09, guarded)
__device__ __forceinline__ float tanh_ratio(float z2) {
    float f = fmaf(z2, fmaf(z2, fmaf(z2, -17.0f/315.0f, 2.0f/15.0f),
                            -1.0f/3.0f), 1.0f);
    if (z2 > 0.09f) {
        float z = sqrtf(z2);
        f = tanhf(fminf(z, 15.0f)) / z;
    }
    return f;
}

__device__ __forceinline__ unsigned cvta_sh(const void* p) {
    return (unsigned)__cvta_generic_to_shared(p);
}

#define ASTRIDE 72
#define NZBLK 1480   // zero/repack blocks appended to the prep grid

// ---------------------------------------------------------------------------
// GEMM prep (tensor cores): proj[row, :] = W @ src[row] (+bias, mode 2).
// 64 rows/block, 128 threads (4 warps) — latency-optimal geometry.
// Mode 3 blocks (appended): zero the edge accumulator AND repack the edge
// index stream; both run concurrently on prep's idle bandwidth/issue slots.
// ---------------------------------------------------------------------------
__global__ __launch_bounds__(128) void prep_gemm(
    const float* __restrict__ Ws, const float* __restrict__ Wr,
    const float* __restrict__ Wqr, const float* __restrict__ hidden,
    const float* __restrict__ rela, const int* __restrict__ q_rel,
    const float* __restrict__ Wqr_b, float* __restrict__ zout, int zcount4,
    const int* __restrict__ edges, int n_edge,
    int n_node, int n_vocab, int nB, int nb0, int nb1, int nb2)
{
    // ---- mode 3: zero + repack blocks ----
    if ((int)blockIdx.x >= nb0 + nb1 + nb2) {
        int zb = blockIdx.x - (nb0 + nb1 + nb2);
        float4 z4 = make_float4(0.f, 0.f, 0.f, 0.f);
        for (int i = zb * 128 + threadIdx.x; i < zcount4; i += NZBLK * 128)
            ((float4*)zout)[i] = z4;
        int ne = (n_edge < MAX_EDGE) ? n_edge : MAX_EDGE;
        for (int e = zb * 128 + threadIdx.x; e < ne; e += NZBLK * 128) {
            const int2* ep = (const int2*)edges + (long)e * 3;
            int2 w0 = __ldcs(ep), w1 = __ldcs(ep + 1), w2 = __ldcs(ep + 2);
            // r_idx = w0.x, rel = w1.x, sub = w2.x, obj = w2.y
            g_epack[e] = make_uint2((unsigned)w2.x | ((unsigned)w1.x << 17),
                                    (unsigned)w2.y | ((unsigned)w0.x << 17));
        }
        return;
    }

    __shared__ __align__(16) __nv_bfloat16 Asm[64 * ASTRIDE];
    __shared__ __align__(16) __nv_bfloat16 Bsm[64 * ASTRIDE];

    int mode, bidx, n_rows;
    const float* W; const float* src;
    if ((int)blockIdx.x < nb0) {
        mode = 0; bidx = blockIdx.x; W = Ws; src = hidden; n_rows = n_node;
    } else if ((int)blockIdx.x < nb0 + nb1) {
        mode = 1; bidx = blockIdx.x - nb0; W = Wr; src = rela; n_rows = n_vocab;
    } else {
        mode = 2; bidx = blockIdx.x - nb0 - nb1; W = Wqr; src = rela; n_rows = nB;
    }
    int base = bidx * 64;

    int t = threadIdx.x;
    int w = t >> 5, lane = t & 31;
    int l16 = lane & 15, hi16 = lane >> 4;

    {
        int k4 = l16 * 4;
#pragma unroll
        for (int i = 0; i < 8; i++) {
            int row = w * 16 + i * 2 + hi16;
            float4 v = __ldg((const float4*)&W[row * DD + k4]);
            *(__nv_bfloat162*)&Bsm[row * ASTRIDE + k4]     = __floats2bfloat162_rn(v.x, v.y);
            *(__nv_bfloat162*)&Bsm[row * ASTRIDE + k4 + 2] = __floats2bfloat162_rn(v.z, v.w);
        }
    }
    {
        int k4 = l16 * 4;
#pragma unroll
        for (int i = 0; i < 8; i++) {
            int rloc = w * 16 + i * 2 + hi16;
            int row = base + rloc;
            float4 v = make_float4(0.f, 0.f, 0.f, 0.f);
            if (row < n_rows) {
                int sr = (mode == 2) ? __ldg(&q_rel[row]) : row;
                v = __ldg((const float4*)&src[sr * DD + k4]);
            }
            *(__nv_bfloat162*)&Asm[rloc * ASTRIDE + k4]     = __floats2bfloat162_rn(v.x, v.y);
            *(__nv_bfloat162*)&Asm[rloc * ASTRIDE + k4 + 2] = __floats2bfloat162_rn(v.z, v.w);
        }
    }
    __syncthreads();

    int m0 = w * 16;
    unsigned a[4][4];
#pragma unroll
    for (int kt = 0; kt < 4; kt++) {
        int arow = m0 + (lane & 15);
        int acol = kt * 16 + (lane >> 4) * 8;
        unsigned addr = cvta_sh(&Asm[arow * ASTRIDE + acol]);
        asm volatile("ldmatrix.sync.aligned.m8n8.x4.shared.b16 {%0,%1,%2,%3}, [%4];"
                     : "=r"(a[kt][0]), "=r"(a[kt][1]), "=r"(a[kt][2]), "=r"(a[kt][3])
                     : "r"(addr));
    }

    __nv_bfloat16* projh = (mode == 0) ? g_hs_projh :
                           (mode == 1) ? g_rel_projh : g_qr_projh;

    int gid = lane >> 2, qid = lane & 3;

#pragma unroll
    for (int nt = 0; nt < 8; nt++) {
        float d0 = 0.f, d1 = 0.f, d2 = 0.f, d3 = 0.f;
#pragma unroll
        for (int kt = 0; kt < 4; kt++) {
            int jrow = nt * 8 + (lane & 7);
            int jcol = kt * 16 + ((lane >> 3) & 1) * 8;
            unsigned baddr = cvta_sh(&Bsm[jrow * ASTRIDE + jcol]);
            unsigned b0, b1;
            asm volatile("ldmatrix.sync.aligned.m8n8.x2.shared.b16 {%0,%1}, [%2];"
                         : "=r"(b0), "=r"(b1) : "r"(baddr));
            asm volatile(
                "mma.sync.aligned.m16n8k16.row.col.f32.bf16.bf16.f32 "
                "{%0,%1,%2,%3}, {%4,%5,%6,%7}, {%8,%9}, {%0,%1,%2,%3};"
                : "+f"(d0), "+f"(d1), "+f"(d2), "+f"(d3)
                : "r"(a[kt][0]), "r"(a[kt][1]), "r"(a[kt][2]), "r"(a[kt][3]),
                  "r"(b0), "r"(b1));
        }

        int col = nt * 8 + qid * 2;
        if (mode == 2) {
            float2 bb = __ldg((const float2*)&Wqr_b[col]);
            d0 += bb.x; d1 += bb.y; d2 += bb.x; d3 += bb.y;
        }
        int row0 = base + m0 + gid;
        int row1 = row0 + 8;
        if (row0 < n_rows)
            *(__nv_bfloat162*)&projh[row0 * DD + col] = __floats2bfloat162_rn(d0, d1);
        if (row1 < n_rows)
            *(__nv_bfloat162*)&projh[row1 * DD + col] = __floats2bfloat162_rn(d2, d3);
    }
}

// ---------------------------------------------------------------------------
// edge kernel: 16 lanes per group, 2 consecutive edges per group per iter.
// Indices come from g_epack: one broadcast uint4 per pair (8B/edge).
// message = sigmoid(attn) * (hidden[sub] + rela_embed[rel])
// ---------------------------------------------------------------------------
struct EdgeVals {
    int obj;
    float s;
    float4 hx, y;
};

__device__ __forceinline__ void edge_load(
    const float* __restrict__ hidden, const float* __restrict__ rela,
    float4 wa, int l, unsigned w0, unsigned w1, EdgeVals& v)
{
    int sub   = w0 & 0x1FFFF;
    int rel   = w0 >> 17;
    int obj   = w1 & 0x1FFFF;
    int r_idx = w1 >> 17;
    v.obj = obj;

    uint2 pb = __ldg((const uint2*)g_hs_projh  + sub   * 16 + l);
    uint2 rb = __ldg((const uint2*)g_rel_projh + rel   * 16 + l);
    uint2 qb = __ldg((const uint2*)g_qr_projh  + r_idx * 16 + l);

    __nv_bfloat162 z2b; *(unsigned*)&z2b = 0u;
    __nv_bfloat162 t0 = __hmax2(__hadd2(__hadd2(*(__nv_bfloat162*)&pb.x,
                                                *(__nv_bfloat162*)&rb.x),
                                        *(__nv_bfloat162*)&qb.x), z2b);
    __nv_bfloat162 t1 = __hmax2(__hadd2(__hadd2(*(__nv_bfloat162*)&pb.y,
                                                *(__nv_bfloat162*)&rb.y),
                                        *(__nv_bfloat162*)&qb.y), z2b);
    unsigned u0 = *(unsigned*)&t0, u1 = *(unsigned*)&t1;
    float s = bflo(u0) * wa.x;
    s = fmaf(bfhi(u0), wa.y, s);
    s = fmaf(bflo(u1), wa.z, s);
    s = fmaf(bfhi(u1), wa.w, s);
    v.s = s;

    v.hx = __ldg((const float4*)hidden + sub * 16 + l);
    v.y  = __ldg((const float4*)rela   + rel * 16 + l);
}

__device__ __forceinline__ void edge_finish(
    const EdgeVals& v, float* __restrict__ out, int l)
{
    float alpha = __fdividef(1.0f, 1.0f + __expf(-v.s));

    float g0 = alpha * (v.hx.x + v.y.x);
    float g1 = alpha * (v.hx.y + v.y.y);
    float g2 = alpha * (v.hx.z + v.y.z);
    float g3 = alpha * (v.hx.w + v.y.w);

    float* dst = out + (long)v.obj * DD + l * 4;
    asm volatile("red.global.add.v4.f32 [%0], {%1,%2,%3,%4};"
                 :: "l"(dst), "f"(g0), "f"(g1), "f"(g2), "f"(g3) : "memory");
}

__global__ __launch_bounds__(256) void edge_kernel(
    const float* __restrict__ Wattn,
    const float* __restrict__ hidden, const float* __restrict__ rela,
    float* __restrict__ out, int n_edge)
{
    int l = threadIdx.x & 15;
    float4 wa = __ldg((const float4*)Wattn + l);
    int group  = (blockIdx.x * blockDim.x + threadIdx.x) >> 4;
    int stride = (gridDim.x * blockDim.x) >> 4;
    int npair  = (n_edge + 1) >> 1;

    int p = group;
    uint4 cur;
    if (p < npair) cur = __ldg((const uint4*)g_epack + p);   // 2 packed edges

    while (p < npair) {
        uint4 c = cur;
        bool has1 = (p * 2 + 1) < n_edge;

        int pn = p + stride;
        if (pn < npair) cur = __ldg((const uint4*)g_epack + pn);

        EdgeVals v0, v1;
        edge_load(hidden, rela, wa, l, c.x, c.y, v0);
        if (has1) edge_load(hidden, rela, wa, l, c.z, c.w, v1);
        else v1.s = 0;

        float a = v0.s, b = v1.s;
#pragma unroll
        for (int o = 8; o; o >>= 1) {
            a += __shfl_xor_sync(0xffffffffu, a, o);
            b += __shfl_xor_sync(0xffffffffu, b, o);
        }
        v0.s = a; v1.s = b;

        edge_finish(v0, out, l);
        if (has1) edge_finish(v1, out, l);

        p = pn;
    }
}

// ---------------------------------------------------------------------------
// final GEMM (tensor cores, split-bf16 for f32-accurate matvec):
// out[n] = logmap0(relu(expmap0(Wh @ agg[n])))  (in-place)
// 64 rows/block, 128 threads, static smem — R11 champion geometry.
// acc = Whi@Ahi + Whi@Alo + Wlo@Ahi  (error ~2^-16).
// ---------------------------------------------------------------------------
__global__ __launch_bounds__(128) void final_gemm(
    const float* __restrict__ Wh, float* __restrict__ out, int n_node)
{
    __shared__ __align__(16) __nv_bfloat16 Ahi[64 * ASTRIDE];
    __shared__ __align__(16) __nv_bfloat16 Alo[64 * ASTRIDE];
    __shared__ __align__(16) __nv_bfloat16 Bhi[64 * ASTRIDE];
    __shared__ __align__(16) __nv_bfloat16 Blo[64 * ASTRIDE];

    int base = blockIdx.x * 64;
    int t = threadIdx.x;
    int w = t >> 5, lane = t & 31;
    int l16 = lane & 15, hi16 = lane >> 4;

    {
        int k4 = l16 * 4;
#pragma unroll
        for (int i = 0; i < 8; i++) {
            int row = w * 16 + i * 2 + hi16;
            float4 v = __ldg((const float4*)&Wh[row * DD + k4]);
            __nv_bfloat16 hx = __float2bfloat16_rn(v.x), hy = __float2bfloat16_rn(v.y);
            __nv_bfloat16 hz = __float2bfloat16_rn(v.z), hw = __float2bfloat16_rn(v.w);
            *(__nv_bfloat162*)&Bhi[row * ASTRIDE + k4]     = __nv_bfloat162(hx, hy);
            *(__nv_bfloat162*)&Bhi[row * ASTRIDE + k4 + 2] = __nv_bfloat162(hz, hw);
            *(__nv_bfloat162*)&Blo[row * ASTRIDE + k4] =
                __floats2bfloat162_rn(v.x - __bfloat162float(hx), v.y - __bfloat162float(hy));
            *(__nv_bfloat162*)&Blo[row * ASTRIDE + k4 + 2] =
                __floats2bfloat162_rn(v.z - __bfloat162float(hz), v.w - __bfloat162float(hw));
        }
    }
    {
        int k4 = l16 * 4;
#pragma unroll
        for (int i = 0; i < 8; i++) {
            int rloc = w * 16 + i * 2 + hi16;
            int row = base + rloc;
            float4 v = make_float4(0.f, 0.f, 0.f, 0.f);
            if (row < n_node) v = __ldg((const float4*)&out[row * DD + k4]);
            __nv_bfloat16 hx = __float2bfloat16_rn(v.x), hy = __float2bfloat16_rn(v.y);
            __nv_bfloat16 hz = __float2bfloat16_rn(v.z), hw = __float2bfloat16_rn(v.w);
            *(__nv_bfloat162*)&Ahi[rloc * ASTRIDE + k4]     = __nv_bfloat162(hx, hy);
            *(__nv_bfloat162*)&Ahi[rloc * ASTRIDE + k4 + 2] = __nv_bfloat162(hz, hw);
            *(__nv_bfloat162*)&Alo[rloc * ASTRIDE + k4] =
                __floats2bfloat162_rn(v.x - __bfloat162float(hx), v.y - __bfloat162float(hy));
            *(__nv_bfloat162*)&Alo[rloc * ASTRIDE + k4 + 2] =
                __floats2bfloat162_rn(v.z - __bfloat162float(hz), v.w - __bfloat162float(hw));
        }
    }
    __syncthreads();

    int m0 = w * 16;
    unsigned ahi[4][4], alo[4][4];
#pragma unroll
    for (int kt = 0; kt < 4; kt++) {
        int arow = m0 + (lane & 15);
        int acol = kt * 16 + (lane >> 4) * 8;
        unsigned addr = cvta_sh(&Ahi[arow * ASTRIDE + acol]);
        asm volatile("ldmatrix.sync.aligned.m8n8.x4.shared.b16 {%0,%1,%2,%3}, [%4];"
                     : "=r"(ahi[kt][0]), "=r"(ahi[kt][1]), "=r"(ahi[kt][2]), "=r"(ahi[kt][3])
                     : "r"(addr));
        unsigned addr2 = cvta_sh(&Alo[arow * ASTRIDE + acol]);
        asm volatile("ldmatrix.sync.aligned.m8n8.x4.shared.b16 {%0,%1,%2,%3}, [%4];"
                     : "=r"(alo[kt][0]), "=r"(alo[kt][1]), "=r"(alo[kt][2]), "=r"(alo[kt][3])
                     : "r"(addr2));
    }

    int gid = lane >> 2, qid = lane & 3;
    float acc0[16], acc1[16];

#pragma unroll
    for (int nt = 0; nt < 8; nt++) {
        float d0 = 0.f, d1 = 0.f, d2 = 0.f, d3 = 0.f;
#pragma unroll
        for (int kt = 0; kt < 4; kt++) {
            int jrow = nt * 8 + (lane & 7);
            int jcol = kt * 16 + ((lane >> 3) & 1) * 8;
            unsigned bh0, bh1, bl0, bl1;
            unsigned baddr = cvta_sh(&Bhi[jrow * ASTRIDE + jcol]);
            asm volatile("ldmatrix.sync.aligned.m8n8.x2.shared.b16 {%0,%1}, [%2];"
                         : "=r"(bh0), "=r"(bh1) : "r"(baddr));
            unsigned baddr2 = cvta_sh(&Blo[jrow * ASTRIDE + jcol]);
            asm volatile("ldmatrix.sync.aligned.m8n8.x2.shared.b16 {%0,%1}, [%2];"
                         : "=r"(bl0), "=r"(bl1) : "r"(baddr2));
            asm volatile(
                "mma.sync.aligned.m16n8k16.row.col.f32.bf16.bf16.f32 "
                "{%0,%1,%2,%3}, {%4,%5,%6,%7}, {%8,%9}, {%0,%1,%2,%3};"
                : "+f"(d0), "+f"(d1), "+f"(d2), "+f"(d3)
                : "r"(ahi[kt][0]), "r"(ahi[kt][1]), "r"(ahi[kt][2]), "r"(ahi[kt][3]),
                  "r"(bh0), "r"(bh1));
            asm volatile(
                "mma.sync.aligned.m16n8k16.row.col.f32.bf16.bf16.f32 "
                "{%0,%1,%2,%3}, {%4,%5,%6,%7}, {%8,%9}, {%0,%1,%2,%3};"
                : "+f"(d0), "+f"(d1), "+f"(d2), "+f"(d3)
                : "r"(ahi[kt][0]), "r"(ahi[kt][1]), "r"(ahi[kt][2]), "r"(ahi[kt][3]),
                  "r"(bl0), "r"(bl1));
            asm volatile(
                "mma.sync.aligned.m16n8k16.row.col.f32.bf16.bf16.f32 "
                "{%0,%1,%2,%3}, {%4,%5,%6,%7}, {%8,%9}, {%0,%1,%2,%3};"
                : "+f"(d0), "+f"(d1), "+f"(d2), "+f"(d3)
                : "r"(alo[kt][0]), "r"(alo[kt][1]), "r"(alo[kt][2]), "r"(alo[kt][3]),
                  "r"(bh0), "r"(bh1));
        }
        acc0[nt * 2] = d0; acc0[nt * 2 + 1] = d1;
        acc1[nt * 2] = d2; acc1[nt * 2 + 1] = d3;
    }

    // fused per-row reductions: quad lanes (same gid) own the same 2 rows
    float sa0 = 0.f, sp0 = 0.f, sa1 = 0.f, sp1 = 0.f;
#pragma unroll
    for (int i = 0; i < 16; i++) {
        float a0 = acc0[i], a1 = acc1[i];
        float p0 = fmaxf(a0, 0.f), p1 = fmaxf(a1, 0.f);
        sa0 = fmaf(a0, a0, sa0); sp0 = fmaf(p0, p0, sp0);
        sa1 = fmaf(a1, a1, sa1); sp1 = fmaf(p1, p1, sp1);
    }
#pragma unroll
    for (int o = 1; o <= 2; o <<= 1) {
        sa0 += __shfl_xor_sync(0xffffffffu, sa0, o);
        sp0 += __shfl_xor_sync(0xffffffffu, sp0, o);
        sa1 += __shfl_xor_sync(0xffffffffu, sa1, o);
        sp1 += __shfl_xor_sync(0xffffffffu, sp1, o);
    }

    float fac0 = tanh_ratio(CC * sa0);
    float rn20 = fac0 * fac0 * sa0;
    float ps0  = (rn20 > MN2) ? MAXNORM * rsqrtf(rn20) : 1.0f;
    float fp0  = fac0 * ps0;
    float gg0  = artanh_ratio(CC * (fp0 * fp0 * sp0));
    float m0s  = fp0 * gg0;

    float fac1 = tanh_ratio(CC * sa1);
    float rn21 = fac1 * fac1 * sa1;
    float ps1  = (rn21 > MN2) ? MAXNORM * rsqrtf(rn21) : 1.0f;
    float fp1  = fac1 * ps1;
    float gg1  = artanh_ratio(CC * (fp1 * fp1 * sp1));
    float m1s  = fp1 * gg1;

    int row0 = base + m0 + gid;
    int row1 = row0 + 8;
#pragma unroll
    for (int nt = 0; nt < 8; nt++) {
        int col = nt * 8 + qid * 2;
        if (row0 < n_node) {
            float2 v = make_float2(m0s * fmaxf(acc0[nt * 2], 0.f),
                                   m0s * fmaxf(acc0[nt * 2 + 1], 0.f));
            *(float2*)&out[row0 * DD + col] = v;
        }
        if (row1 < n_node) {
            float2 v = make_float2(m1s * fmaxf(acc1[nt * 2], 0.f),
                                   m1s * fmaxf(acc1[nt * 2 + 1], 0.f));
            *(float2*)&out[row1 * DD + col] = v;
        }
    }
}

// ---------------------------------------------------------------------------
extern "C" void kernel_launch(void* const* d_in, const int* in_sizes, int n_in,
                              void* d_out, int out_size)
{
    const float* hidden = (const float*)d_in[0];
    const int*   q_rel  = (const int*)  d_in[1];
    const int*   edges  = (const int*)  d_in[2];
    const float* rela   = (const float*)d_in[3];
    const float* Ws     = (const float*)d_in[4];
    const float* Wr     = (const float*)d_in[5];
    const float* Wqr    = (const float*)d_in[6];
    const float* Wqr_b  = (const float*)d_in[7];
    const float* Wattn  = (const float*)d_in[8];
    const float* Wh     = (const float*)d_in[9];
    float* out = (float*)d_out;

    int n_node  = in_sizes[0] / DD;
    int Bn      = in_sizes[1];
    int n_edge  = in_sizes[2] / 6;
    int n_vocab = in_sizes[3] / DD;

    int nb0 = (n_node  + 63) / 64;
    int nb1 = (n_vocab + 63) / 64;
    int nb2 = (Bn      + 63) / 64;

    // prep GEMM blocks + zero/repack blocks
    prep_gemm<<<nb0 + nb1 + nb2 + NZBLK, 128>>>(
        Ws, Wr, Wqr, hidden, rela, q_rel, Wqr_b,
        out, out_size / 4, edges, n_edge, n_node, n_vocab, Bn, nb0, nb1, nb2);

    edge_kernel<<<2368, 256>>>(Wattn, hidden, rela, out, n_edge);

    final_gemm<<<nb0, 128>>>(Wh, out, n_node);
}

// round 15
// speedup vs baseline: 1.0954x; 1.0954x over previous
#include <cuda_runtime.h>
#include <cuda_bf16.h>
#include <math.h>

// ---------------------------------------------------------------------------
// GNNModel: hyperbolic GNN message passing (c = 1e-6)
//
// Edge path: with c=1e-6 and data scale 0.1, expmap0/mobius/logmap0 are
// identity to O(1e-6) relative (tolerance 1e-3):
//   message = sigmoid(attn) * (hidden[sub] + rela_embed[rel])
// Final per-node transform keeps exact math via split-bf16 tensor-core GEMM.
// Edge kernel L1 policy: cold gathers (hidden, hs_projh) use .cg (L2-only)
// so the hot tables (rel_projh/qr_projh/rela, 186KB) stay L1-resident.
// ---------------------------------------------------------------------------

#define MAX_NODE 100000
#define MAX_VOCAB 512
#define MAX_B 256
#define DD 64

// attention tables in bf16 (only feed sigmoid(relu(.)@Wattn) — error << 1e-3)
__device__ __align__(16) __nv_bfloat16 g_hs_projh [MAX_NODE * DD];
__device__ __align__(16) __nv_bfloat16 g_rel_projh[MAX_VOCAB * DD];
__device__ __align__(16) __nv_bfloat16 g_qr_projh [MAX_B * DD];

#define SC 1.0e-3f                    // sqrt(c), c = 1e-6
#define CC 1.0e-6f
#define MAXNORM (0.996f / SC)
#define MN2 (MAXNORM * MAXNORM)

// bf16 pair (packed in u32) -> two f32, pure ALU
__device__ __forceinline__ float bflo(unsigned u) { return __uint_as_float(u << 16); }
__device__ __forceinline__ float bfhi(unsigned u) { return __uint_as_float(u & 0xffff0000u); }

// artanh(z)/z as poly in z^2 (valid z^2 < 0.09, guarded fallback above)
__device__ __forceinline__ float artanh_ratio(float z2) {
    float f = fmaf(z2, fmaf(z2, fmaf(z2, fmaf(z2, 1.0f/9.0f, 1.0f/7.0f),
                                     0.2f), 1.0f/3.0f), 1.0f);
    if (z2 > 0.09f) {
        float z = sqrtf(z2);
        float zc = fminf(z, 1.0f - 1e-5f);
        f = 0.5f * (log1pf(zc) - log1pf(-zc)) / z;
    }
    return f;
}
// tanh(z)/z as poly in z^2 (valid z^2 < 0.09, guarded)
__device__ __forceinline__ float tanh_ratio(float z2) {
    float f = fmaf(z2, fmaf(z2, fmaf(z2, -17.0f/315.0f, 2.0f/15.0f),
                            -1.0f/3.0f), 1.0f);
    if (z2 > 0.09f) {
        float z = sqrtf(z2);
        f = tanhf(fminf(z, 15.0f)) / z;
    }
    return f;
}

__device__ __forceinline__ unsigned cvta_sh(const void* p) {
    return (unsigned)__cvta_generic_to_shared(p);
}

#define ASTRIDE 72
#define NZBLK 1480   // zero-only blocks appended to the prep grid

// ---------------------------------------------------------------------------
// GEMM prep (tensor cores): proj[row, :] = W @ src[row] (+bias, mode 2).
// 64 rows/block, 128 threads (4 warps) — latency-optimal geometry.
// Mode 3 blocks (appended) only zero the edge accumulator; they run
// concurrently with the GEMM blocks on prep's idle DRAM bandwidth.
// ---------------------------------------------------------------------------
__global__ __launch_bounds__(128) void prep_gemm(
    const float* __restrict__ Ws, const float* __restrict__ Wr,
    const float* __restrict__ Wqr, const float* __restrict__ hidden,
    const float* __restrict__ rela, const int* __restrict__ q_rel,
    const float* __restrict__ Wqr_b, float* __restrict__ zout, int zcount4,
    int n_node, int n_vocab, int nB, int nb0, int nb1, int nb2)
{
    // ---- mode 3: zero-only blocks ----
    if ((int)blockIdx.x >= nb0 + nb1 + nb2) {
        int zb = blockIdx.x - (nb0 + nb1 + nb2);
        float4 z4 = make_float4(0.f, 0.f, 0.f, 0.f);
        for (int i = zb * 128 + threadIdx.x; i < zcount4; i += NZBLK * 128)
            ((float4*)zout)[i] = z4;
        return;
    }

    __shared__ __align__(16) __nv_bfloat16 Asm[64 * ASTRIDE];
    __shared__ __align__(16) __nv_bfloat16 Bsm[64 * ASTRIDE];

    int mode, bidx, n_rows;
    const float* W; const float* src;
    if ((int)blockIdx.x < nb0) {
        mode = 0; bidx = blockIdx.x; W = Ws; src = hidden; n_rows = n_node;
    } else if ((int)blockIdx.x < nb0 + nb1) {
        mode = 1; bidx = blockIdx.x - nb0; W = Wr; src = rela; n_rows = n_vocab;
    } else {
        mode = 2; bidx = blockIdx.x - nb0 - nb1; W = Wqr; src = rela; n_rows = nB;
    }
    int base = bidx * 64;

    int t = threadIdx.x;
    int w = t >> 5, lane = t & 31;
    int l16 = lane & 15, hi16 = lane >> 4;

    {
        int k4 = l16 * 4;
#pragma unroll
        for (int i = 0; i < 8; i++) {
            int row = w * 16 + i * 2 + hi16;
            float4 v = __ldg((const float4*)&W[row * DD + k4]);
            *(__nv_bfloat162*)&Bsm[row * ASTRIDE + k4]     = __floats2bfloat162_rn(v.x, v.y);
            *(__nv_bfloat162*)&Bsm[row * ASTRIDE + k4 + 2] = __floats2bfloat162_rn(v.z, v.w);
        }
    }
    {
        int k4 = l16 * 4;
#pragma unroll
        for (int i = 0; i < 8; i++) {
            int rloc = w * 16 + i * 2 + hi16;
            int row = base + rloc;
            float4 v = make_float4(0.f, 0.f, 0.f, 0.f);
            if (row < n_rows) {
                int sr = (mode == 2) ? __ldg(&q_rel[row]) : row;
                v = __ldg((const float4*)&src[sr * DD + k4]);
            }
            *(__nv_bfloat162*)&Asm[rloc * ASTRIDE + k4]     = __floats2bfloat162_rn(v.x, v.y);
            *(__nv_bfloat162*)&Asm[rloc * ASTRIDE + k4 + 2] = __floats2bfloat162_rn(v.z, v.w);
        }
    }
    __syncthreads();

    int m0 = w * 16;
    unsigned a[4][4];
#pragma unroll
    for (int kt = 0; kt < 4; kt++) {
        int arow = m0 + (lane & 15);
        int acol = kt * 16 + (lane >> 4) * 8;
        unsigned addr = cvta_sh(&Asm[arow * ASTRIDE + acol]);
        asm volatile("ldmatrix.sync.aligned.m8n8.x4.shared.b16 {%0,%1,%2,%3}, [%4];"
                     : "=r"(a[kt][0]), "=r"(a[kt][1]), "=r"(a[kt][2]), "=r"(a[kt][3])
                     : "r"(addr));
    }

    __nv_bfloat16* projh = (mode == 0) ? g_hs_projh :
                           (mode == 1) ? g_rel_projh : g_qr_projh;

    int gid = lane >> 2, qid = lane & 3;

#pragma unroll
    for (int nt = 0; nt < 8; nt++) {
        float d0 = 0.f, d1 = 0.f, d2 = 0.f, d3 = 0.f;
#pragma unroll
        for (int kt = 0; kt < 4; kt++) {
            int jrow = nt * 8 + (lane & 7);
            int jcol = kt * 16 + ((lane >> 3) & 1) * 8;
            unsigned baddr = cvta_sh(&Bsm[jrow * ASTRIDE + jcol]);
            unsigned b0, b1;
            asm volatile("ldmatrix.sync.aligned.m8n8.x2.shared.b16 {%0,%1}, [%2];"
                         : "=r"(b0), "=r"(b1) : "r"(baddr));
            asm volatile(
                "mma.sync.aligned.m16n8k16.row.col.f32.bf16.bf16.f32 "
                "{%0,%1,%2,%3}, {%4,%5,%6,%7}, {%8,%9}, {%0,%1,%2,%3};"
                : "+f"(d0), "+f"(d1), "+f"(d2), "+f"(d3)
                : "r"(a[kt][0]), "r"(a[kt][1]), "r"(a[kt][2]), "r"(a[kt][3]),
                  "r"(b0), "r"(b1));
        }

        int col = nt * 8 + qid * 2;
        if (mode == 2) {
            float2 bb = __ldg((const float2*)&Wqr_b[col]);
            d0 += bb.x; d1 += bb.y; d2 += bb.x; d3 += bb.y;
        }
        int row0 = base + m0 + gid;
        int row1 = row0 + 8;
        if (row0 < n_rows)
            *(__nv_bfloat162*)&projh[row0 * DD + col] = __floats2bfloat162_rn(d0, d1);
        if (row1 < n_rows)
            *(__nv_bfloat162*)&projh[row1 * DD + col] = __floats2bfloat162_rn(d2, d3);
    }
}

// ---------------------------------------------------------------------------
// edge kernel: 16 lanes per group, 2 consecutive edges per group per iter,
// edge indices software-pipelined; packed bf16x2 attention math.
// Cold gathers use .cg (L2-only) so hot tables stay L1-resident.
// message = sigmoid(attn) * (hidden[sub] + rela_embed[rel])
// ---------------------------------------------------------------------------
struct EdgeVals {
    int obj;
    float s;
    float4 hx, y;
};

__device__ __forceinline__ void edge_load(
    const float* __restrict__ hidden, const float* __restrict__ rela,
    float4 wa, int l, int r_idx, int rel, int sub, int obj, EdgeVals& v)
{
    v.obj = obj;

    // cold gather (12.8MB table): L2-only, keep out of L1
    uint2 pb = __ldcg((const uint2*)g_hs_projh  + sub   * 16 + l);
    // hot tables (51KB + 33KB): default L1 caching
    uint2 rb = __ldg((const uint2*)g_rel_projh + rel   * 16 + l);
    uint2 qb = __ldg((const uint2*)g_qr_projh  + r_idx * 16 + l);

    __nv_bfloat162 z2b; *(unsigned*)&z2b = 0u;
    __nv_bfloat162 t0 = __hmax2(__hadd2(__hadd2(*(__nv_bfloat162*)&pb.x,
                                                *(__nv_bfloat162*)&rb.x),
                                        *(__nv_bfloat162*)&qb.x), z2b);
    __nv_bfloat162 t1 = __hmax2(__hadd2(__hadd2(*(__nv_bfloat162*)&pb.y,
                                                *(__nv_bfloat162*)&rb.y),
                                        *(__nv_bfloat162*)&qb.y), z2b);
    unsigned u0 = *(unsigned*)&t0, u1 = *(unsigned*)&t1;
    float s = bflo(u0) * wa.x;
    s = fmaf(bfhi(u0), wa.y, s);
    s = fmaf(bflo(u1), wa.z, s);
    s = fmaf(bfhi(u1), wa.w, s);
    v.s = s;

    // cold gather (25.6MB): L2-only
    v.hx = __ldcg((const float4*)hidden + sub * 16 + l);
    // hot table (102KB): L1
    v.y  = __ldg((const float4*)rela   + rel * 16 + l);
}

__device__ __forceinline__ void edge_finish(
    const EdgeVals& v, float* __restrict__ out, int l)
{
    float alpha = __fdividef(1.0f, 1.0f + __expf(-v.s));

    float g0 = alpha * (v.hx.x + v.y.x);
    float g1 = alpha * (v.hx.y + v.y.y);
    float g2 = alpha * (v.hx.z + v.y.z);
    float g3 = alpha * (v.hx.w + v.y.w);

    float* dst = out + (long)v.obj * DD + l * 4;
    asm volatile("red.global.add.v4.f32 [%0], {%1,%2,%3,%4};"
                 :: "l"(dst), "f"(g0), "f"(g1), "f"(g2), "f"(g3) : "memory");
}

__global__ __launch_bounds__(256) void edge_kernel(
    const int* __restrict__ edges, const float* __restrict__ Wattn,
    const float* __restrict__ hidden, const float* __restrict__ rela,
    float* __restrict__ out, int n_edge)
{
    int l = threadIdx.x & 15;
    float4 wa = __ldg((const float4*)Wattn + l);
    int group  = (blockIdx.x * blockDim.x + threadIdx.x) >> 4;
    int stride = (gridDim.x * blockDim.x) >> 4;
    int npair  = (n_edge + 1) >> 1;

    int p = group;
    int2 c0a, c0b, c0c, c1a, c1b, c1c;
    if (p < npair) {
        const int2* e0 = (const int2*)edges + (long)(p * 2) * 3;
        c0a = __ldcs(e0); c0b = __ldcs(e0 + 1); c0c = __ldcs(e0 + 2);
        if (p * 2 + 1 < n_edge) {
            c1a = __ldcs(e0 + 3); c1b = __ldcs(e0 + 4); c1c = __ldcs(e0 + 5);
        } else { c1a = c0a; c1b = c0b; c1c = c0c; }
    }

    while (p < npair) {
        int2 i0a = c0a, i0b = c0b, i0c = c0c;
        int2 i1a = c1a, i1b = c1b, i1c = c1c;
        bool has1 = (p * 2 + 1) < n_edge;

        int pn = p + stride;
        if (pn < npair) {
            const int2* e0 = (const int2*)edges + (long)(pn * 2) * 3;
            c0a = __ldcs(e0); c0b = __ldcs(e0 + 1); c0c = __ldcs(e0 + 2);
            if (pn * 2 + 1 < n_edge) {
                c1a = __ldcs(e0 + 3); c1b = __ldcs(e0 + 4); c1c = __ldcs(e0 + 5);
            }
        }

        EdgeVals v0, v1;
        edge_load(hidden, rela, wa, l, i0a.x, i0b.x, i0c.x, i0c.y, v0);
        if (has1) edge_load(hidden, rela, wa, l, i1a.x, i1b.x, i1c.x, i1c.y, v1);
        else v1.s = 0;

        float a = v0.s, b = v1.s;
#pragma unroll
        for (int o = 8; o; o >>= 1) {
            a += __shfl_xor_sync(0xffffffffu, a, o);
            b += __shfl_xor_sync(0xffffffffu, b, o);
        }
        v0.s = a; v1.s = b;

        edge_finish(v0, out, l);
        if (has1) edge_finish(v1, out, l);

        p = pn;
    }
}

// ---------------------------------------------------------------------------
// final GEMM (tensor cores, split-bf16 for f32-accurate matvec):
// out[n] = logmap0(relu(expmap0(Wh @ agg[n])))  (in-place)
// 64 rows/block, 128 threads, static smem — champion geometry.
// acc = Whi@Ahi + Whi@Alo + Wlo@Ahi  (error ~2^-16).
// ---------------------------------------------------------------------------
__global__ __launch_bounds__(128) void final_gemm(
    const float* __restrict__ Wh, float* __restrict__ out, int n_node)
{
    __shared__ __align__(16) __nv_bfloat16 Ahi[64 * ASTRIDE];
    __shared__ __align__(16) __nv_bfloat16 Alo[64 * ASTRIDE];
    __shared__ __align__(16) __nv_bfloat16 Bhi[64 * ASTRIDE];
    __shared__ __align__(16) __nv_bfloat16 Blo[64 * ASTRIDE];

    int base = blockIdx.x * 64;
    int t = threadIdx.x;
    int w = t >> 5, lane = t & 31;
    int l16 = lane & 15, hi16 = lane >> 4;

    {
        int k4 = l16 * 4;
#pragma unroll
        for (int i = 0; i < 8; i++) {
            int row = w * 16 + i * 2 + hi16;
            float4 v = __ldg((const float4*)&Wh[row * DD + k4]);
            __nv_bfloat16 hx = __float2bfloat16_rn(v.x), hy = __float2bfloat16_rn(v.y);
            __nv_bfloat16 hz = __float2bfloat16_rn(v.z), hw = __float2bfloat16_rn(v.w);
            *(__nv_bfloat162*)&Bhi[row * ASTRIDE + k4]     = __nv_bfloat162(hx, hy);
            *(__nv_bfloat162*)&Bhi[row * ASTRIDE + k4 + 2] = __nv_bfloat162(hz, hw);
            *(__nv_bfloat162*)&Blo[row * ASTRIDE + k4] =
                __floats2bfloat162_rn(v.x - __bfloat162float(hx), v.y - __bfloat162float(hy));
            *(__nv_bfloat162*)&Blo[row * ASTRIDE + k4 + 2] =
                __floats2bfloat162_rn(v.z - __bfloat162float(hz), v.w - __bfloat162float(hw));
        }
    }
    {
        int k4 = l16 * 4;
#pragma unroll
        for (int i = 0; i < 8; i++) {
            int rloc = w * 16 + i * 2 + hi16;
            int row = base + rloc;
            float4 v = make_float4(0.f, 0.f, 0.f, 0.f);
            if (row < n_node) v = __ldg((const float4*)&out[row * DD + k4]);
            __nv_bfloat16 hx = __float2bfloat16_rn(v.x), hy = __float2bfloat16_rn(v.y);
            __nv_bfloat16 hz = __float2bfloat16_rn(v.z), hw = __float2bfloat16_rn(v.w);
            *(__nv_bfloat162*)&Ahi[rloc * ASTRIDE + k4]     = __nv_bfloat162(hx, hy);
            *(__nv_bfloat162*)&Ahi[rloc * ASTRIDE + k4 + 2] = __nv_bfloat162(hz, hw);
            *(__nv_bfloat162*)&Alo[rloc * ASTRIDE + k4] =
                __floats2bfloat162_rn(v.x - __bfloat162float(hx), v.y - __bfloat162float(hy));
            *(__nv_bfloat162*)&Alo[rloc * ASTRIDE + k4 + 2] =
                __floats2bfloat162_rn(v.z - __bfloat162float(hz), v.w - __bfloat162float(hw));
        }
    }
    __syncthreads();

    int m0 = w * 16;
    unsigned ahi[4][4], alo[4][4];
#pragma unroll
    for (int kt = 0; kt < 4; kt++) {
        int arow = m0 + (lane & 15);
        int acol = kt * 16 + (lane >> 4) * 8;
        unsigned addr = cvta_sh(&Ahi[arow * ASTRIDE + acol]);
        asm volatile("ldmatrix.sync.aligned.m8n8.x4.shared.b16 {%0,%1,%2,%3}, [%4];"
                     : "=r"(ahi[kt][0]), "=r"(ahi[kt][1]), "=r"(ahi[kt][2]), "=r"(ahi[kt][3])
                     : "r"(addr));
        unsigned addr2 = cvta_sh(&Alo[arow * ASTRIDE + acol]);
        asm volatile("ldmatrix.sync.aligned.m8n8.x4.shared.b16 {%0,%1,%2,%3}, [%4];"
                     : "=r"(alo[kt][0]), "=r"(alo[kt][1]), "=r"(alo[kt][2]), "=r"(alo[kt][3])
                     : "r"(addr2));
    }

    int gid = lane >> 2, qid = lane & 3;
    float acc0[16], acc1[16];

#pragma unroll
    for (int nt = 0; nt < 8; nt++) {
        float d0 = 0.f, d1 = 0.f, d2 = 0.f, d3 = 0.f;
#pragma unroll
        for (int kt = 0; kt < 4; kt++) {
            int jrow = nt * 8 + (lane & 7);
            int jcol = kt * 16 + ((lane >> 3) & 1) * 8;
            unsigned bh0, bh1, bl0, bl1;
            unsigned baddr = cvta_sh(&Bhi[jrow * ASTRIDE + jcol]);
            asm volatile("ldmatrix.sync.aligned.m8n8.x2.shared.b16 {%0,%1}, [%2];"
                         : "=r"(bh0), "=r"(bh1) : "r"(baddr));
            unsigned baddr2 = cvta_sh(&Blo[jrow * ASTRIDE + jcol]);
            asm volatile("ldmatrix.sync.aligned.m8n8.x2.shared.b16 {%0,%1}, [%2];"
                         : "=r"(bl0), "=r"(bl1) : "r"(baddr2));
            asm volatile(
                "mma.sync.aligned.m16n8k16.row.col.f32.bf16.bf16.f32 "
                "{%0,%1,%2,%3}, {%4,%5,%6,%7}, {%8,%9}, {%0,%1,%2,%3};"
                : "+f"(d0), "+f"(d1), "+f"(d2), "+f"(d3)
                : "r"(ahi[kt][0]), "r"(ahi[kt][1]), "r"(ahi[kt][2]), "r"(ahi[kt][3]),
                  "r"(bh0), "r"(bh1));
            asm volatile(
                "mma.sync.aligned.m16n8k16.row.col.f32.bf16.bf16.f32 "
                "{%0,%1,%2,%3}, {%4,%5,%6,%7}, {%8,%9}, {%0,%1,%2,%3};"
                : "+f"(d0), "+f"(d1), "+f"(d2), "+f"(d3)
                : "r"(ahi[kt][0]), "r"(ahi[kt][1]), "r"(ahi[kt][2]), "r"(ahi[kt][3]),
                  "r"(bl0), "r"(bl1));
            asm volatile(
                "mma.sync.aligned.m16n8k16.row.col.f32.bf16.bf16.f32 "
                "{%0,%1,%2,%3}, {%4,%5,%6,%7}, {%8,%9}, {%0,%1,%2,%3};"
                : "+f"(d0), "+f"(d1), "+f"(d2), "+f"(d3)
                : "r"(alo[kt][0]), "r"(alo[kt][1]), "r"(alo[kt][2]), "r"(alo[kt][3]),
                  "r"(bh0), "r"(bh1));
        }
        acc0[nt * 2] = d0; acc0[nt * 2 + 1] = d1;
        acc1[nt * 2] = d2; acc1[nt * 2 + 1] = d3;
    }

    // fused per-row reductions: quad lanes (same gid) own the same 2 rows
    float sa0 = 0.f, sp0 = 0.f, sa1 = 0.f, sp1 = 0.f;
#pragma unroll
    for (int i = 0; i < 16; i++) {
        float a0 = acc0[i], a1 = acc1[i];
        float p0 = fmaxf(a0, 0.f), p1 = fmaxf(a1, 0.f);
        sa0 = fmaf(a0, a0, sa0); sp0 = fmaf(p0, p0, sp0);
        sa1 = fmaf(a1, a1, sa1); sp1 = fmaf(p1, p1, sp1);
    }
#pragma unroll
    for (int o = 1; o <= 2; o <<= 1) {
        sa0 += __shfl_xor_sync(0xffffffffu, sa0, o);
        sp0 += __shfl_xor_sync(0xffffffffu, sp0, o);
        sa1 += __shfl_xor_sync(0xffffffffu, sa1, o);
        sp1 += __shfl_xor_sync(0xffffffffu, sp1, o);
    }

    float fac0 = tanh_ratio(CC * sa0);
    float rn20 = fac0 * fac0 * sa0;
    float ps0  = (rn20 > MN2) ? MAXNORM * rsqrtf(rn20) : 1.0f;
    float fp0  = fac0 * ps0;
    float gg0  = artanh_ratio(CC * (fp0 * fp0 * sp0));
    float m0s  = fp0 * gg0;

    float fac1 = tanh_ratio(CC * sa1);
    float rn21 = fac1 * fac1 * sa1;
    float ps1  = (rn21 > MN2) ? MAXNORM * rsqrtf(rn21) : 1.0f;
    float fp1  = fac1 * ps1;
    float gg1  = artanh_ratio(CC * (fp1 * fp1 * sp1));
    float m1s  = fp1 * gg1;

    int row0 = base + m0 + gid;
    int row1 = row0 + 8;
#pragma unroll
    for (int nt = 0; nt < 8; nt++) {
        int col = nt * 8 + qid * 2;
        if (row0 < n_node) {
            float2 v = make_float2(m0s * fmaxf(acc0[nt * 2], 0.f),
                                   m0s * fmaxf(acc0[nt * 2 + 1], 0.f));
            *(float2*)&out[row0 * DD + col] = v;
        }
        if (row1 < n_node) {
            float2 v = make_float2(m1s * fmaxf(acc1[nt * 2], 0.f),
                                   m1s * fmaxf(acc1[nt * 2 + 1], 0.f));
            *(float2*)&out[row1 * DD + col] = v;
        }
    }
}

// ---------------------------------------------------------------------------
extern "C" void kernel_launch(void* const* d_in, const int* in_sizes, int n_in,
                              void* d_out, int out_size)
{
    const float* hidden = (const float*)d_in[0];
    const int*   q_rel  = (const int*)  d_in[1];
    const int*   edges  = (const int*)  d_in[2];
    const float* rela   = (const float*)d_in[3];
    const float* Ws     = (const float*)d_in[4];
    const float* Wr     = (const float*)d_in[5];
    const float* Wqr    = (const float*)d_in[6];
    const float* Wqr_b  = (const float*)d_in[7];
    const float* Wattn  = (const float*)d_in[8];
    const float* Wh     = (const float*)d_in[9];
    float* out = (float*)d_out;

    int n_node  = in_sizes[0] / DD;
    int Bn      = in_sizes[1];
    int n_edge  = in_sizes[2] / 6;
    int n_vocab = in_sizes[3] / DD;

    int nb0 = (n_node  + 63) / 64;
    int nb1 = (n_vocab + 63) / 64;
    int nb2 = (Bn      + 63) / 64;

    // prep GEMM blocks + NZBLK zero-only blocks (replaces the memset node)
    prep_gemm<<<nb0 + nb1 + nb2 + NZBLK, 128>>>(
        Ws, Wr, Wqr, hidden, rela, q_rel, Wqr_b,
        out, out_size / 4, n_node, n_vocab, Bn, nb0, nb1, nb2);

    edge_kernel<<<2368, 256>>>(edges, Wattn, hidden, rela, out, n_edge);

    final_gemm<<<nb0, 128>>>(Wh, out, n_node);
}